// round 7
// baseline (speedup 1.0000x reference)
#include <cuda_runtime.h>
#include <math.h>

#define BATCH 8
#define FEAT 512
#define NUM 512
#define KK 32
#define NSPLIT 4
#define NBLK 256

typedef unsigned long long ull;

// 1/sqrt(512): global L2 scale is exact (512 unit-norm rows per half)
#define GSC 0.04419417382415922f

// ---------------- device scratch (static, allocation-free) ----------------
__device__ float g_a[BATCH * NUM * KK];               // a[b][n][k]
__device__ float g_axp[NSPLIT * BATCH * FEAT * KK];   // partial ax  [s][b][f][k]
__device__ float g_ax2p[NSPLIT * BATCH * FEAT * KK];  // partial ax2 [s][b][f][k]
__device__ float g_asumt[BATCH * KK * 16];            // asum partials TRANSPOSED [b][k][tile]
__device__ unsigned g_cnt = 0;                        // barrier counter (self-resets)
__device__ unsigned g_gen = 0;                        // barrier generation (monotonic)

__device__ __forceinline__ float wsum(float v) {
#pragma unroll
    for (int o = 16; o; o >>= 1) v += __shfl_xor_sync(0xffffffffu, v, o);
    return v;
}
__device__ __forceinline__ float wmax(float v) {
#pragma unroll
    for (int o = 16; o; o >>= 1) v = fmaxf(v, __shfl_xor_sync(0xffffffffu, v, o));
    return v;
}

// packed f32x2 helpers (sm_100+)
__device__ __forceinline__ ull pk(float lo, float hi) {
    ull r;
    asm("mov.b64 %0, {%1, %2};" : "=l"(r) : "f"(lo), "f"(hi));
    return r;
}
__device__ __forceinline__ void upk(float& lo, float& hi, ull v) {
    asm("mov.b64 {%0, %1}, %2;" : "=f"(lo), "=f"(hi) : "l"(v));
}
__device__ __forceinline__ void ffma2(ull& d, ull a, ull b) {
    asm("fma.rn.f32x2 %0, %1, %2, %0;" : "+l"(d) : "l"(a), "l"(b));
}
__device__ __forceinline__ ull fmul2(ull a, ull b) {
    ull r;
    asm("mul.rn.f32x2 %0, %1, %2;" : "=l"(r) : "l"(a), "l"(b));
    return r;
}

// Replay-safe grid barrier. Waiters poll with volatile loads; counter
// self-resets; generation monotonic.
__device__ __forceinline__ void gridbar() {
    __threadfence();
    __syncthreads();
    if (threadIdx.x == 0) {
        unsigned gen = *((volatile unsigned*)&g_gen);
        if (atomicAdd(&g_cnt, 1u) == NBLK - 1u) {
            *((volatile unsigned*)&g_cnt) = 0u;
            __threadfence();
            atomicAdd(&g_gen, 1u);
        } else {
            while (*((volatile unsigned*)&g_gen) == gen) __nanosleep(64);
        }
        __threadfence();
    }
    __syncthreads();
}

// shared-memory phase union (33,024 B total, static -> occ 2 guaranteed)
struct P1 {
    ull   W2[KK][65];      // W dup'd (w,w); odd 8B stride -> conflict-free LDS64
    float X_s[64][32];     // [f_local][n_local]; LDS128 warp-broadcast
    float red[8][KK];
};
struct P2 {
    float A_s[128][32];    // FULL n-range a tile [n][k]; LDS128 broadcast
    float Xh[64][65];      // raw x half-tile [f][n]; odd stride -> conflict-free LDS32
};
union SMU {
    P1 p1;
    P2 p2;
};

// ---------------- single kernel: softmax -> bar -> gemm -> bar -> fv ---------
__global__ __launch_bounds__(256, 2) void k_all(const float* __restrict__ x,
                                                const float* __restrict__ W,
                                                const float* __restrict__ bias,
                                                const float* __restrict__ mu,
                                                const float* __restrict__ sigma,
                                                float* __restrict__ out) {
    __shared__ __align__(16) SMU sm;
    const int tid  = threadIdx.x;
    const int w    = tid >> 5;
    const int lane = tid & 31;
    const int bx   = blockIdx.x;

    // phase-2 coords
    const int ft2 = bx & 7;
    const int s2  = (bx >> 3) & 3;
    const int b2  = bx >> 5;
    const int f02 = ft2 * 64;
    const int nb2 = s2 * 128;

    // ================= PHASE 1: logits + softmax + asum partials =============
    // 128 CTAs: b = bx>>4, 32-n tile = bx&15. Warp owns 4 n's (2 f32x2 chains).
    if (bx < 128) {
        const int b    = bx >> 4;
        const int tile = bx & 15;
        const int n0   = tile * 32;

        ull acc01 = 0ULL, acc23 = 0ULL;

        float wr[8], xr[8];
#pragma unroll
        for (int i = 0; i < 8; i++) {
            int idx = tid + i * 256;
            wr[i] = W[(idx >> 6) * FEAT + (idx & 63)];
            xr[i] = x[((size_t)b * FEAT + (idx >> 5)) * NUM + n0 + (idx & 31)];
        }

        for (int t = 0; t < 8; t++) {
            __syncthreads();
#pragma unroll
            for (int i = 0; i < 8; i++) {
                int idx = tid + i * 256;
                sm.p1.W2[idx >> 6][idx & 63] = pk(wr[i], wr[i]);
                sm.p1.X_s[idx >> 5][idx & 31] = xr[i];
            }
            __syncthreads();
            if (t < 7) {
                const int fb = (t + 1) * 64;
#pragma unroll
                for (int i = 0; i < 8; i++) {
                    int idx = tid + i * 256;
                    wr[i] = W[(idx >> 6) * FEAT + fb + (idx & 63)];
                    xr[i] = x[((size_t)b * FEAT + fb + (idx >> 5)) * NUM + n0 + (idx & 31)];
                }
            }
#pragma unroll 8
            for (int fl = 0; fl < 64; fl++) {
                ull wvv = sm.p1.W2[lane][fl];                                             // LDS64 cf
                ulonglong2 xp = *reinterpret_cast<const ulonglong2*>(&sm.p1.X_s[fl][w * 4]); // LDS128 bc
                ffma2(acc01, wvv, xp.x);
                ffma2(acc23, wvv, xp.y);
            }
        }

        float l[4];
        upk(l[0], l[1], acc01);
        upk(l[2], l[3], acc23);

        const float bv = bias[lane];
        float pa = 0.f;
#pragma unroll
        for (int j = 0; j < 4; j++) {
            float lg = l[j] + bv;
            float m = wmax(lg);
            float e = __expf(lg - m);
            float s = wsum(e);
            float a = e / s;
            int   n = n0 + w * 4 + j;
            g_a[((size_t)b * NUM + n) * KK + lane] = a;
            pa += a;
        }
        sm.p1.red[w][lane] = pa;
        __syncthreads();
        if (tid < 32) {
            float s = 0.f;
#pragma unroll
            for (int g = 0; g < 8; g++) s += sm.p1.red[g][tid];
            g_asumt[((size_t)b * KK + tid) * 16 + tile] = s;
        }
    }

    __syncthreads();   // p1 fully read before Xh (overlapping region) is written

    // stage X half 0 pre-barrier: input-only dependency; phase-1-idle CTAs do
    // this during their barrier wait, so the load time is free for them.
#pragma unroll
    for (int i = 0; i < 4; i++) {
        int idx = tid + i * 256;
        int fr = idx >> 4, q = (idx & 15) * 4;
        float4 v = *reinterpret_cast<const float4*>(
            &x[((size_t)b2 * FEAT + f02 + fr) * NUM + nb2 + q]);
        float* d = &sm.p2.Xh[fr][q];
        d[0] = v.x; d[1] = v.y; d[2] = v.z; d[3] = v.w;
    }

    gridbar();

    // ================= PHASE 2: ax / ax2 GEMM partials ========================
    {
        const int fw = w & 1, kg = w >> 1;
        const int fl = fw * 32 + lane;     // f within tile (per-lane, odd-stride cf)
        const int kbase = kg * 8;          // 8 k's = 4 packed pairs per thread

        // stage FULL A tile [128 n][32 k] (one exposure, MLP=4 LDG.128/thread)
#pragma unroll
        for (int i = 0; i < 4; i++) {
            int idx = tid + i * 256;
            int nl = idx >> 3, kq = (idx & 7) * 4;
            float4 v = *reinterpret_cast<const float4*>(
                &g_a[((size_t)b2 * NUM + nb2 + nl) * KK + kq]);
            *reinterpret_cast<float4*>(&sm.p2.A_s[nl][kq]) = v;
        }
        __syncthreads();

        ull acc1[4] = {0ULL, 0ULL, 0ULL, 0ULL};
        ull acc2[4] = {0ULL, 0ULL, 0ULL, 0ULL};

#pragma unroll
        for (int h = 0; h < 2; h++) {
            if (h == 1) {
                // swap in second n-half of X (A tile persists)
                __syncthreads();
#pragma unroll
                for (int i = 0; i < 4; i++) {
                    int idx = tid + i * 256;
                    int fr = idx >> 4, q = (idx & 15) * 4;
                    float4 v = *reinterpret_cast<const float4*>(
                        &x[((size_t)b2 * FEAT + f02 + fr) * NUM + nb2 + 64 + q]);
                    float* d = &sm.p2.Xh[fr][q];
                    d[0] = v.x; d[1] = v.y; d[2] = v.z; d[3] = v.w;
                }
                __syncthreads();
            }
            const int nbase = h * 64;
#pragma unroll 8
            for (int nl = 0; nl < 64; nl++) {
                float xv = sm.p2.Xh[fl][nl];     // LDS32, conflict-free (odd stride 65)
                ull xvv  = pk(xv, xv);
                ull x2vv = fmul2(xvv, xvv);      // packed x^2
                const float* arow = &sm.p2.A_s[nbase + nl][kbase];
                ulonglong2 a01 = *reinterpret_cast<const ulonglong2*>(arow);      // LDS128 bc
                ulonglong2 a23 = *reinterpret_cast<const ulonglong2*>(arow + 4);  // LDS128 bc
                ffma2(acc1[0], a01.x, xvv);  ffma2(acc2[0], a01.x, x2vv);
                ffma2(acc1[1], a01.y, xvv);  ffma2(acc2[1], a01.y, x2vv);
                ffma2(acc1[2], a23.x, xvv);  ffma2(acc2[2], a23.x, x2vv);
                ffma2(acc1[3], a23.y, xvv);  ffma2(acc2[3], a23.y, x2vv);
            }
        }

        const size_t base = (((size_t)s2 * BATCH + b2) * FEAT + f02 + fl) * KK + kbase;
        *reinterpret_cast<ulonglong2*>(&g_axp[base])      = make_ulonglong2(acc1[0], acc1[1]);
        *reinterpret_cast<ulonglong2*>(&g_axp[base + 4])  = make_ulonglong2(acc1[2], acc1[3]);
        *reinterpret_cast<ulonglong2*>(&g_ax2p[base])     = make_ulonglong2(acc2[0], acc2[1]);
        *reinterpret_cast<ulonglong2*>(&g_ax2p[base + 4]) = make_ulonglong2(acc2[2], acc2[3]);
    }

    gridbar();

    // ================= PHASE 3: fisher vectors + rownorm + const scale ========
    // 256 CTAs, 2 fg units each (8 f's per unit): b = bx>>5, fgbase = (bx&31)*2.
    {
        const int b      = bx >> 5;
        const int fgbase = (bx & 31) * 2;

        // asum[b][k]: 16 contiguous partials -> 4x LDG.128
        float asv = 0.f;
        {
            const float4* p = reinterpret_cast<const float4*>(&g_asumt[((size_t)b * KK + lane) * 16]);
#pragma unroll
            for (int q = 0; q < 4; q++) {
                float4 v = p[q];
                asv += (v.x + v.y) + (v.z + v.w);
            }
        }

#pragma unroll
        for (int j = 0; j < 2; j++) {
            const int f = (fgbase + j) * 8 + w;
            float ax = 0.f, ax2 = 0.f;
#pragma unroll
            for (int s = 0; s < NSPLIT; s++) {
                size_t po = (((size_t)s * BATCH + b) * FEAT + f) * KK + lane;
                ax  += g_axp[po];
                ax2 += g_ax2p[po];
            }
            float muv = mu[f * KK + lane];
            float sg  = sigma[f * KK + lane];
            float fv1 = (ax - muv * asv) / sg;
            float fv2 = (ax2 - 2.f * muv * ax + muv * muv * asv) / (sg * sg) - asv;

            float n1 = sqrtf(wsum(fv1 * fv1));
            float n2 = sqrtf(wsum(fv2 * fv2));
            float v1 = fv1 / fmaxf(n1, 1e-12f) * GSC;
            float v2 = fv2 / fmaxf(n2, 1e-12f) * GSC;

            const size_t ob = (size_t)b * 2 * FEAT * KK;
            out[ob + (size_t)f * KK + lane]             = v1;
            out[ob + FEAT * KK + (size_t)f * KK + lane] = v2;
        }
    }
}

// ---------------- launch -----------------------------------------------------
extern "C" void kernel_launch(void* const* d_in, const int* in_sizes, int n_in,
                              void* d_out, int out_size) {
    (void)in_sizes; (void)n_in; (void)out_size;
    const float* x     = (const float*)d_in[0];
    const float* W     = (const float*)d_in[1];
    const float* bias  = (const float*)d_in[2];
    const float* mu    = (const float*)d_in[3];
    const float* sigma = (const float*)d_in[4];
    float* out = (float*)d_out;

    k_all<<<NBLK, 256>>>(x, W, bias, mu, sigma, out);
}